// round 14
// baseline (speedup 1.0000x reference)
#include <cuda_runtime.h>
#include <cuda_bf16.h>
#include <math.h>
#include <stdint.h>

// ---------------- problem constants ----------------
#define Bv 8
#define Cv 2
#define Tv 1440000
#define Mv 1024
#define Nv 2048
#define Fv 1408
#define Rv (Bv*Fv*Cv)                // 22528 rows
#define NFRAME (Bv*Fv)               // 11264

// ---------------- static scratch ----------------
__device__ float g_W  [Nv];
__device__ float g_Cm [Nv*Mv];            // fwd B fp32: [n 2048][m 1024]
__device__ float g_FR [(size_t)Rv*Nv];    // fwd A fp32
__device__ float g_CO [(size_t)Rv*Mv];    // MDCT coeffs fp32
__device__ float g_GA [NFRAME];
__device__ float g_TD [(size_t)Rv*Nv];    // inverse transform fp32
// bf16 double splits (inverse GEMM only; 3-term emulation)
__device__ __nv_bfloat16 g_DQh[(size_t)Rv*Mv], g_DQm[(size_t)Rv*Mv];
__device__ __nv_bfloat16 g_BIh[Nv*Mv], g_BIm[Nv*Mv];   // inv B [n][k=m]

// ---------------- helpers ----------------
__device__ __forceinline__ void bsplit2(float v, __nv_bfloat16* h, __nv_bfloat16* m) {
    __nv_bfloat16 hh = __float2bfloat16_rn(v);
    float r1 = v - __bfloat162float(hh);
    *h = hh; *m = __float2bfloat16_rn(r1);
}
__device__ __forceinline__ uint64_t splat2(float x) {
    uint64_t r; uint32_t u = __float_as_uint(x);
    asm("mov.b64 %0, {%1, %1};" : "=l"(r) : "r"(u));
    return r;
}
__device__ __forceinline__ void ffma2(uint64_t& d, uint64_t a, uint64_t b) {
    asm("fma.rn.f32x2 %0, %1, %2, %0;" : "+l"(d) : "l"(a), "l"(b));
}
__device__ __forceinline__ void fadd2(uint64_t& d, uint64_t a) {
    asm("add.rn.f32x2 %0, %0, %1;" : "+l"(d) : "l"(a));
}
__device__ __forceinline__ float lo32(uint64_t v) {
    return __uint_as_float((uint32_t)(v & 0xffffffffu));
}
__device__ __forceinline__ float hi32(uint64_t v) {
    return __uint_as_float((uint32_t)(v >> 32));
}
__device__ __forceinline__ void mma16(float* d, const uint32_t* a, const uint32_t* b) {
    asm volatile(
        "mma.sync.aligned.m16n8k16.row.col.f32.bf16.bf16.f32 "
        "{%0,%1,%2,%3}, {%4,%5,%6,%7}, {%8,%9}, {%0,%1,%2,%3};"
        : "+f"(d[0]), "+f"(d[1]), "+f"(d[2]), "+f"(d[3])
        : "r"(a[0]), "r"(a[1]), "r"(a[2]), "r"(a[3]), "r"(b[0]), "r"(b[1]));
}
__device__ __forceinline__ void cpa16(uint32_t saddr, const void* g) {
    asm volatile("cp.async.cg.shared.global [%0], [%1], 16;"
                 :: "r"(saddr), "l"(g) : "memory");
}

// ---------------- tables: identical cos numerics to round 3 --------------
__global__ void k_tables() {
    int idx = blockIdx.x * blockDim.x + threadIdx.x;
    if (idx >= Nv * Mv) return;
    int n = idx >> 10;
    int k = idx & 1023;
    const float c0 = (float)(3.14159265358979323846 / 1024.0);
    float a   = c0 * ((float)n + 512.5f);
    float arg = a * ((float)k + 0.5f);
    float v   = cosf(arg);
    g_Cm[n * Mv + k] = v;                       // fwd B fp32 [n][m]
    __nv_bfloat16 h, m;
    bsplit2(v, &h, &m);
    g_BIh[n * Mv + k] = h;                      // inv B [n][k=m]
    g_BIm[n * Mv + k] = m;
    if (idx < Nv) {
        const float c1 = (float)(3.14159265358979323846 / 2048.0);
        g_W[idx] = sinf(c1 * ((float)idx + 0.5f));
    }
}

// ---------------- frame + window (fp32) -----------------------------------
__global__ void k_frames(const float* __restrict__ audio) {
    long long idx = (long long)blockIdx.x * blockDim.x + threadIdx.x;
    if (idx >= (long long)Rv * Nv) return;
    int n   = (int)(idx & (Nv - 1));
    int row = (int)(idx >> 11);
    int c   = row & 1;
    int bf  = row >> 1;
    int f   = bf % Fv;
    int b   = bf / Fv;
    int src = f * Mv + n - Mv;
    float x = (src >= 0 && src < Tv)
                ? audio[(size_t)(b * Cv + c) * Tv + src] : 0.0f;
    g_FR[idx] = x * g_W[n];
}

// ---------------- fwd GEMM v2: 512 threads, 4x8 thread tiles --------------
// Same 128x128 CTA tile, BK=8 double-buffered, same k order and fold points
// as rounds 4/9/13 => bit-identical coefficients; 2x warps per SMSP.
__device__ __forceinline__ void sgemm_fwd() {
    const float* __restrict__ A = g_FR;
    const float* __restrict__ B = g_Cm;
    float* __restrict__ Co = g_CO;
    constexpr int K = Nv, NC = Mv;
    __shared__ float As[2][8][128];
    __shared__ float Bs[2][8][128];
    const int tid  = threadIdx.x;
    const int bx   = blockIdx.x;
    const int by   = blockIdx.y;
    const int tx   = tid & 15;        // col group (8 cols)
    const int ty   = tid >> 4;        // 0..31, row group (4 rows)

    const int arow  = tid >> 2;            // 0..127
    const int acolk = (tid & 3) << 1;      // 0,2,4,6
    const int brow  = tid >> 6;            // 0..7
    const int bcol  = (tid & 63) << 1;     // 0..126

    const float* Ap = A + (size_t)(by * 128 + arow) * K + acolk;
    const float* Bp = B + (size_t)brow * NC + bx * 128 + bcol;

    uint64_t accT[2][8], accC[2][8];
#pragma unroll
    for (int i = 0; i < 2; i++)
#pragma unroll
        for (int j = 0; j < 8; j++) { accT[i][j] = 0ull; accC[i][j] = 0ull; }

    {   // prologue: tile 0
        float2 a2 = *(const float2*)Ap;
        float2 b2 = *(const float2*)Bp;
        As[0][acolk    ][arow] = a2.x;
        As[0][acolk + 1][arow] = a2.y;
        *(float2*)&Bs[0][brow][bcol] = b2;
    }
    __syncthreads();

    const int NT = K / 8;
    int buf = 0;
#pragma unroll 1
    for (int t = 0; t < NT; ++t) {
        float2 na2, nb2;
        const bool have_next = (t + 1 < NT);
        if (have_next) {
            na2 = *(const float2*)(Ap + (size_t)(t + 1) * 8);
            nb2 = *(const float2*)(Bp + (size_t)(t + 1) * 8 * NC);
        }
#pragma unroll
        for (int k = 0; k < 8; k++) {
            ulonglong2 av = *(const ulonglong2*)&As[buf][k][ty * 4];
            uint64_t ap0 = av.x, ap1 = av.y;    // rows ty*4+{0,1}, ty*4+{2,3}
            float rb[8];
            *(float4*)&rb[0] = *(const float4*)&Bs[buf][k][tx * 8];
            *(float4*)&rb[4] = *(const float4*)&Bs[buf][k][tx * 8 + 4];
            uint64_t bs[8];
#pragma unroll
            for (int j = 0; j < 8; j++) bs[j] = splat2(rb[j]);
#pragma unroll
            for (int j = 0; j < 8; j++) {
                ffma2(accC[0][j], ap0, bs[j]);
                ffma2(accC[1][j], ap1, bs[j]);
            }
        }
        if (((t + 1) & 31) == 0) {              // fold every 256 k
#pragma unroll
            for (int i = 0; i < 2; i++)
#pragma unroll
                for (int j = 0; j < 8; j++) {
                    fadd2(accT[i][j], accC[i][j]);
                    accC[i][j] = 0ull;
                }
        }
        if (have_next) {
            int nbuf = buf ^ 1;
            As[nbuf][acolk    ][arow] = na2.x;
            As[nbuf][acolk + 1][arow] = na2.y;
            *(float2*)&Bs[nbuf][brow][bcol] = nb2;
            __syncthreads();
            buf = nbuf;
        }
    }

    float* Cp = Co + (size_t)(by * 128 + ty * 4) * NC + bx * 128 + tx * 8;
#pragma unroll
    for (int i = 0; i < 4; i++) {
        const int i2 = i >> 1;
        float4 o0, o1;
        if ((i & 1) == 0) {
            o0.x = lo32(accT[i2][0]); o0.y = lo32(accT[i2][1]);
            o0.z = lo32(accT[i2][2]); o0.w = lo32(accT[i2][3]);
            o1.x = lo32(accT[i2][4]); o1.y = lo32(accT[i2][5]);
            o1.z = lo32(accT[i2][6]); o1.w = lo32(accT[i2][7]);
        } else {
            o0.x = hi32(accT[i2][0]); o0.y = hi32(accT[i2][1]);
            o0.z = hi32(accT[i2][2]); o0.w = hi32(accT[i2][3]);
            o1.x = hi32(accT[i2][4]); o1.y = hi32(accT[i2][5]);
            o1.z = hi32(accT[i2][6]); o1.w = hi32(accT[i2][7]);
        }
        *(float4*)(Cp + (size_t)i * NC)     = o0;
        *(float4*)(Cp + (size_t)i * NC + 4) = o1;
    }
}
__global__ __launch_bounds__(512, 1) void k_gemm_fwd() { sgemm_fwd(); }

// ---------------- inv GEMM: bf16x2 (3-term) mma, BK=32, 2-stage -----------
// Terms hh + hm + mh; dropped mm/hl/lh ~ 2^-18 each (linear output error).
// Dynamic SMEM 2x40960B. Per-array region 128 rows x 40 bf16 (80B rows).
__device__ __forceinline__ void bf_inv() {
    constexpr int KTOT = Mv, NC = Nv;
    extern __shared__ char sm[];
    const uint32_t uS = (uint32_t)__cvta_generic_to_shared(sm);
    const uint32_t* us = (const uint32_t*)sm;

    const int tid  = threadIdx.x;
    const int bx   = blockIdx.x, by = blockIdx.y;
    const int lane = tid & 31, wid = tid >> 5;
    const int wm   = (wid & 3) * 32;
    const int wn   = (wid >> 2) * 64;
    const int qr   = lane >> 2, qc = lane & 3;

    float acc[2][8][4];
#pragma unroll
    for (int i = 0; i < 2; i++)
#pragma unroll
        for (int j = 0; j < 8; j++)
#pragma unroll
            for (int c = 0; c < 4; c++) acc[i][j][c] = 0.0f;

    auto load_stage = [&](int s) {
        const uint32_t sb = (uint32_t)(s & 1) * 40960u;
        const int kt = s * 32;
#pragma unroll
        for (int i = 0; i < 2; i++) {
            const int idx = tid + i * 256;           // all 128 rows
            const int r  = idx >> 2;
            const int cc = idx & 3;
            const uint32_t soff = (uint32_t)(r * 80 + cc * 16);
            size_t ga = (size_t)(by * 128 + r) * KTOT + kt + cc * 8;
            cpa16(uS + sb +     0u + soff, g_DQh + ga);
            cpa16(uS + sb + 10240u + soff, g_DQm + ga);
            size_t gb = (size_t)(bx * 128 + r) * KTOT + kt + cc * 8;
            cpa16(uS + sb + 20480u + soff, g_BIh + gb);
            cpa16(uS + sb + 30720u + soff, g_BIm + gb);
        }
        asm volatile("cp.async.commit_group;" ::: "memory");
    };

    constexpr int NST = KTOT / 32;
    load_stage(0);
    load_stage(1);

#pragma unroll 1
    for (int s = 0; s < NST; s++) {
        if (s + 1 < NST)
            asm volatile("cp.async.wait_group 1;" ::: "memory");
        else
            asm volatile("cp.async.wait_group 0;" ::: "memory");
        __syncthreads();

        const int so4 = (s & 1) * 10240;             // stage offset in u32
#pragma unroll
        for (int ks = 0; ks < 2; ks++) {
            uint32_t Af[2][2][4];
#pragma unroll
            for (int v = 0; v < 2; v++)
#pragma unroll
                for (int mt = 0; mt < 2; mt++) {
                    int r0 = wm + mt * 16 + qr;
                    int base = so4 + v * 2560 + r0 * 20 + ks * 8 + qc;
                    Af[v][mt][0] = us[base];
                    Af[v][mt][1] = us[base + 160];
                    Af[v][mt][2] = us[base + 4];
                    Af[v][mt][3] = us[base + 164];
                }
#pragma unroll
            for (int nt = 0; nt < 8; nt++) {
                int n0 = wn + nt * 8 + qr;
                uint32_t Bf[2][2];
#pragma unroll
                for (int v = 0; v < 2; v++) {
                    int bb = so4 + (2 + v) * 2560 + n0 * 20 + ks * 8 + qc;
                    Bf[v][0] = us[bb];
                    Bf[v][1] = us[bb + 4];
                }
#pragma unroll
                for (int mt = 0; mt < 2; mt++) {
                    mma16(acc[mt][nt], Af[0][mt], Bf[0]);   // h*h
                    mma16(acc[mt][nt], Af[0][mt], Bf[1]);   // h*m
                    mma16(acc[mt][nt], Af[1][mt], Bf[0]);   // m*h
                }
            }
        }
        __syncthreads();
        if (s + 2 < NST) load_stage(s + 2);
    }

    const float sc = 2.0f / 1024.0f;
    float* __restrict__ Co = g_TD;
#pragma unroll
    for (int mt = 0; mt < 2; mt++)
#pragma unroll
        for (int nt = 0; nt < 8; nt++) {
            int rr = by * 128 + wm + mt * 16 + qr;
            int cb = bx * 128 + wn + nt * 8 + qc * 2;
            float2 v0 = make_float2(acc[mt][nt][0] * sc, acc[mt][nt][1] * sc);
            float2 v1 = make_float2(acc[mt][nt][2] * sc, acc[mt][nt][3] * sc);
            *(float2*)(Co + (size_t)rr * NC + cb)       = v0;
            *(float2*)(Co + (size_t)(rr + 8) * NC + cb) = v1;
        }
}
__global__ __launch_bounds__(256, 2) void k_bf_inv() { bf_inv(); }

// ---------------- per-(b,f) gain (round-10 version) -----------------------
__global__ void k_gain() {
    __shared__ int warpsum[8];
    __shared__ float s_lo, s_hi;
    const int bf   = blockIdx.x;
    const int tid  = threadIdx.x;
    const int lane = tid & 31, wid = tid >> 5;
    const float* cf = g_CO + (size_t)bf * 2048;

    float axr[8];
#pragma unroll
    for (int j = 0; j < 8; j++)
        axr[j] = powf(fabsf(cf[tid + j * 256]), 0.75f);

    if (tid == 0) { s_lo = 0.0f; s_hi = 120.0f; }
    __syncthreads();

    const float TARGET = (float)(128000.0 * 1024.0 / 48000.0);
#pragma unroll 1
    for (int it = 0; it < 8; it++) {
        float mid = floorf((s_lo + s_hi) * 0.5f);
        float inv = exp2f((-0.75f * mid) / 4.0f);
        int bits = 0;
#pragma unroll
        for (int j = 0; j < 8; j++) {
            int qi = (int)rintf(axr[j] * inv);
            bits += (qi > 0) ? (33 - __clz(qi)) : 1;
        }
#pragma unroll
        for (int o = 16; o > 0; o >>= 1)
            bits += __shfl_down_sync(0xffffffffu, bits, o);
        if (lane == 0) warpsum[wid] = bits;
        __syncthreads();
        if (tid == 0) {
            int tot = 0;
#pragma unroll
            for (int w = 0; w < 8; w++) tot += warpsum[w];
            if ((float)tot > TARGET) s_lo = mid + 1.0f;
            else                     s_hi = mid;
        }
        __syncthreads();
    }
    if (tid == 0) g_GA[bf] = s_hi;
}

// ---------------- quantize + dequantize + bf16 double split ---------------
__global__ void k_quant() {
    int idx = blockIdx.x * blockDim.x + threadIdx.x;
    if (idx >= Rv * Mv) return;
    int bf = idx >> 11;
    float g     = g_GA[bf];
    float scale = exp2f(g / 4.0f);
    float cv    = g_CO[idx];
    float s1 = (cv > 0.0f) ? 1.0f : ((cv < 0.0f) ? -1.0f : 0.0f);
    float qs = s1 * powf(fabsf(cv) / scale + 1e-9f, 0.75f);
    float q  = rintf(qs);
    float s2 = (q > 0.0f) ? 1.0f : ((q < 0.0f) ? -1.0f : 0.0f);
    float v  = s2 * powf(fabsf(q), (float)(4.0 / 3.0)) * scale;
    __nv_bfloat16 h, m;
    bsplit2(v, &h, &m);
    g_DQh[idx] = h; g_DQm[idx] = m;
}

// ---------------- window + overlap-add + crop ------------------------------
__global__ void k_ola(float* __restrict__ out) {
    int idx = blockIdx.x * blockDim.x + threadIdx.x;
    if (idx >= Bv * Cv * Tv) return;
    int t  = idx % Tv;
    int bc = idx / Tv;
    int b  = bc >> 1;
    int c  = bc & 1;
    int fb = t >> 10;
    int na = t & 1023;
    int rowa = (b * Fv + fb + 1) * Cv + c;
    int rowb = (b * Fv + fb) * Cv + c;
    float r1 = g_TD[(size_t)rowa * Nv + na]      * g_W[na];
    float r2 = g_TD[(size_t)rowb * Nv + na + Mv] * g_W[na + Mv];
    out[idx] = r1 + r2;
}

// ---------------- launch ----------------------------------------------------
extern "C" void kernel_launch(void* const* d_in, const int* in_sizes, int n_in,
                              void* d_out, int out_size) {
    const float* audio = (const float*)d_in[0];
    float* out = (float*)d_out;
    const int SMEM_BYTES = 2 * 40960;   // 81,920 B

    cudaFuncSetAttribute(k_bf_inv, cudaFuncAttributeMaxDynamicSharedMemorySize, SMEM_BYTES);

    k_tables<<<(Nv * Mv + 255) / 256, 256>>>();
    {
        long long tot = (long long)Rv * Nv;
        k_frames<<<(unsigned)((tot + 255) / 256), 256>>>(audio);
    }
    k_gemm_fwd<<<dim3(Mv / 128, Rv / 128), 512>>>();
    k_gain<<<NFRAME, 256>>>();
    k_quant<<<(Rv * Mv + 255) / 256, 256>>>();
    k_bf_inv<<<dim3(Nv / 128, Rv / 128), 256, SMEM_BYTES>>>();
    k_ola<<<(Bv * Cv * Tv + 255) / 256, 256>>>(out);
}

// round 15
// speedup vs baseline: 1.3675x; 1.3675x over previous
#include <cuda_runtime.h>
#include <cuda_bf16.h>
#include <math.h>
#include <stdint.h>

// ---------------- problem constants ----------------
#define Bv 8
#define Cv 2
#define Tv 1440000
#define Mv 1024
#define Nv 2048
#define Fv 1408
#define Rv (Bv*Fv*Cv)                // 22528 rows
#define NFRAME (Bv*Fv)               // 11264

// ---------------- static scratch ----------------
__device__ float g_W  [Nv];
__device__ float g_Cm [Nv*Mv];            // fwd B fp32: [n 2048][m 1024]
__device__ float g_FR [(size_t)Rv*Nv];    // fwd A fp32
__device__ float g_CO [(size_t)Rv*Mv];    // MDCT coeffs fp32
__device__ float g_GA [NFRAME];
__device__ float g_TD [(size_t)Rv*Nv];    // inverse transform fp32
// bf16 double splits (inverse GEMM only; 3-term emulation)
__device__ __nv_bfloat16 g_DQh[(size_t)Rv*Mv], g_DQm[(size_t)Rv*Mv];
__device__ __nv_bfloat16 g_BIh[Nv*Mv], g_BIm[Nv*Mv];   // inv B [n][k=m]

// ---------------- helpers ----------------
__device__ __forceinline__ void bsplit2(float v, __nv_bfloat16* h, __nv_bfloat16* m) {
    __nv_bfloat16 hh = __float2bfloat16_rn(v);
    float r1 = v - __bfloat162float(hh);
    *h = hh; *m = __float2bfloat16_rn(r1);
}
__device__ __forceinline__ uint64_t splat2(float x) {
    uint64_t r; uint32_t u = __float_as_uint(x);
    asm("mov.b64 %0, {%1, %1};" : "=l"(r) : "r"(u));
    return r;
}
__device__ __forceinline__ void ffma2(uint64_t& d, uint64_t a, uint64_t b) {
    asm("fma.rn.f32x2 %0, %1, %2, %0;" : "+l"(d) : "l"(a), "l"(b));
}
__device__ __forceinline__ void fadd2(uint64_t& d, uint64_t a) {
    asm("add.rn.f32x2 %0, %0, %1;" : "+l"(d) : "l"(a));
}
__device__ __forceinline__ float lo32(uint64_t v) {
    return __uint_as_float((uint32_t)(v & 0xffffffffu));
}
__device__ __forceinline__ float hi32(uint64_t v) {
    return __uint_as_float((uint32_t)(v >> 32));
}
__device__ __forceinline__ void mma16(float* d, const uint32_t* a, const uint32_t* b) {
    asm volatile(
        "mma.sync.aligned.m16n8k16.row.col.f32.bf16.bf16.f32 "
        "{%0,%1,%2,%3}, {%4,%5,%6,%7}, {%8,%9}, {%0,%1,%2,%3};"
        : "+f"(d[0]), "+f"(d[1]), "+f"(d[2]), "+f"(d[3])
        : "r"(a[0]), "r"(a[1]), "r"(a[2]), "r"(a[3]), "r"(b[0]), "r"(b[1]));
}
__device__ __forceinline__ void cpa16(uint32_t saddr, const void* g) {
    asm volatile("cp.async.cg.shared.global [%0], [%1], 16;"
                 :: "r"(saddr), "l"(g) : "memory");
}

// ---------------- tables: identical cos numerics to round 3 --------------
__global__ void k_tables() {
    int idx = blockIdx.x * blockDim.x + threadIdx.x;
    if (idx >= Nv * Mv) return;
    int n = idx >> 10;
    int k = idx & 1023;
    const float c0 = (float)(3.14159265358979323846 / 1024.0);
    float a   = c0 * ((float)n + 512.5f);
    float arg = a * ((float)k + 0.5f);
    float v   = cosf(arg);
    g_Cm[n * Mv + k] = v;                       // fwd B fp32 [n][m]
    __nv_bfloat16 h, m;
    bsplit2(v, &h, &m);
    g_BIh[n * Mv + k] = h;                      // inv B [n][k=m]
    g_BIm[n * Mv + k] = m;
    if (idx < Nv) {
        const float c1 = (float)(3.14159265358979323846 / 2048.0);
        g_W[idx] = sinf(c1 * ((float)idx + 0.5f));
    }
}

// ---------------- frame + window (fp32) -----------------------------------
__global__ void k_frames(const float* __restrict__ audio) {
    long long idx = (long long)blockIdx.x * blockDim.x + threadIdx.x;
    if (idx >= (long long)Rv * Nv) return;
    int n   = (int)(idx & (Nv - 1));
    int row = (int)(idx >> 11);
    int c   = row & 1;
    int bf  = row >> 1;
    int f   = bf % Fv;
    int b   = bf / Fv;
    int src = f * Mv + n - Mv;
    float x = (src >= 0 && src < Tv)
                ? audio[(size_t)(b * Cv + c) * Tv + src] : 0.0f;
    g_FR[idx] = x * g_W[n];
}

// ---------------- fwd GEMM: round-13 f32x2 FFMA kernel (bit-frozen) -------
// 256 threads, 8x8 thread tiles, BK=8 double-buffered. DO NOT ALTER:
// coefficients must stay bit-identical (gain search sits on integer edges).
__device__ __forceinline__ void sgemm_fwd() {
    const float* __restrict__ A = g_FR;
    const float* __restrict__ B = g_Cm;
    float* __restrict__ Co = g_CO;
    constexpr int K = Nv, NC = Mv;
    __shared__ float As[2][8][128];
    __shared__ float Bs[2][8][128];
    const int tid  = threadIdx.x;
    const int bx   = blockIdx.x;
    const int by   = blockIdx.y;
    const int arow = tid >> 1;
    const int acol = (tid & 1) << 2;
    const int brow = tid >> 5;
    const int bcol = (tid & 31) << 2;
    const int tx   = tid & 15;
    const int ty   = tid >> 4;

    const float* Ap = A + (size_t)(by * 128 + arow) * K + acol;
    const float* Bp = B + (size_t)brow * NC + bx * 128 + bcol;

    uint64_t accT[4][8], accC[4][8];
#pragma unroll
    for (int i = 0; i < 4; i++)
#pragma unroll
        for (int j = 0; j < 8; j++) { accT[i][j] = 0ull; accC[i][j] = 0ull; }

    {
        float4 a4 = *(const float4*)Ap;
        float4 b4 = *(const float4*)Bp;
        As[0][acol + 0][arow] = a4.x;
        As[0][acol + 1][arow] = a4.y;
        As[0][acol + 2][arow] = a4.z;
        As[0][acol + 3][arow] = a4.w;
        *(float4*)&Bs[0][brow][bcol] = b4;
    }
    __syncthreads();

    const int NT = K / 8;
    int buf = 0;
#pragma unroll 1
    for (int t = 0; t < NT; ++t) {
        float4 na, nb4;
        const bool have_next = (t + 1 < NT);
        if (have_next) {
            na  = *(const float4*)(Ap + (size_t)(t + 1) * 8);
            nb4 = *(const float4*)(Bp + (size_t)(t + 1) * 8 * NC);
        }
#pragma unroll
        for (int k = 0; k < 8; k++) {
            uint64_t ap[4];
            {
                const ulonglong2* p2 = (const ulonglong2*)&As[buf][k][ty * 8];
                ulonglong2 v0 = p2[0], v1 = p2[1];
                ap[0] = v0.x; ap[1] = v0.y; ap[2] = v1.x; ap[3] = v1.y;
            }
            float rb[8];
            *(float4*)&rb[0] = *(const float4*)&Bs[buf][k][tx * 8];
            *(float4*)&rb[4] = *(const float4*)&Bs[buf][k][tx * 8 + 4];
            uint64_t bs[8];
#pragma unroll
            for (int j = 0; j < 8; j++) bs[j] = splat2(rb[j]);
#pragma unroll
            for (int i = 0; i < 4; i++)
#pragma unroll
                for (int j = 0; j < 8; j++)
                    ffma2(accC[i][j], ap[i], bs[j]);
        }
        if (((t + 1) & 31) == 0) {
#pragma unroll
            for (int i = 0; i < 4; i++)
#pragma unroll
                for (int j = 0; j < 8; j++) {
                    fadd2(accT[i][j], accC[i][j]);
                    accC[i][j] = 0ull;
                }
        }
        if (have_next) {
            int nbuf = buf ^ 1;
            As[nbuf][acol + 0][arow] = na.x;
            As[nbuf][acol + 1][arow] = na.y;
            As[nbuf][acol + 2][arow] = na.z;
            As[nbuf][acol + 3][arow] = na.w;
            *(float4*)&Bs[nbuf][brow][bcol] = nb4;
            __syncthreads();
            buf = nbuf;
        }
    }

    float* Cp = Co + (size_t)(by * 128 + ty * 8) * NC + bx * 128 + tx * 8;
#pragma unroll
    for (int i = 0; i < 8; i++) {
        const int i2 = i >> 1;
        float4 o0, o1;
        if ((i & 1) == 0) {
            o0.x = lo32(accT[i2][0]); o0.y = lo32(accT[i2][1]);
            o0.z = lo32(accT[i2][2]); o0.w = lo32(accT[i2][3]);
            o1.x = lo32(accT[i2][4]); o1.y = lo32(accT[i2][5]);
            o1.z = lo32(accT[i2][6]); o1.w = lo32(accT[i2][7]);
        } else {
            o0.x = hi32(accT[i2][0]); o0.y = hi32(accT[i2][1]);
            o0.z = hi32(accT[i2][2]); o0.w = hi32(accT[i2][3]);
            o1.x = hi32(accT[i2][4]); o1.y = hi32(accT[i2][5]);
            o1.z = hi32(accT[i2][6]); o1.w = hi32(accT[i2][7]);
        }
        *(float4*)(Cp + (size_t)i * NC)     = o0;
        *(float4*)(Cp + (size_t)i * NC + 4) = o1;
    }
}
__global__ __launch_bounds__(256, 1) void k_gemm_fwd() { sgemm_fwd(); }

// ---------------- inv GEMM: bf16x2 (3-term) mma, BK=32, 2-stage -----------
// Terms hh + hm + mh; dropped mm/hl/lh ~ 2^-18 each (linear output error).
// Dynamic SMEM 2x40960B. Per-array region 128 rows x 40 bf16 (80B rows).
__device__ __forceinline__ void bf_inv() {
    constexpr int KTOT = Mv, NC = Nv;
    extern __shared__ char sm[];
    const uint32_t uS = (uint32_t)__cvta_generic_to_shared(sm);
    const uint32_t* us = (const uint32_t*)sm;

    const int tid  = threadIdx.x;
    const int bx   = blockIdx.x, by = blockIdx.y;
    const int lane = tid & 31, wid = tid >> 5;
    const int wm   = (wid & 3) * 32;
    const int wn   = (wid >> 2) * 64;
    const int qr   = lane >> 2, qc = lane & 3;

    float acc[2][8][4];
#pragma unroll
    for (int i = 0; i < 2; i++)
#pragma unroll
        for (int j = 0; j < 8; j++)
#pragma unroll
            for (int c = 0; c < 4; c++) acc[i][j][c] = 0.0f;

    auto load_stage = [&](int s) {
        const uint32_t sb = (uint32_t)(s & 1) * 40960u;
        const int kt = s * 32;
#pragma unroll
        for (int i = 0; i < 2; i++) {
            const int idx = tid + i * 256;           // all 128 rows
            const int r  = idx >> 2;
            const int cc = idx & 3;
            const uint32_t soff = (uint32_t)(r * 80 + cc * 16);
            size_t ga = (size_t)(by * 128 + r) * KTOT + kt + cc * 8;
            cpa16(uS + sb +     0u + soff, g_DQh + ga);
            cpa16(uS + sb + 10240u + soff, g_DQm + ga);
            size_t gb = (size_t)(bx * 128 + r) * KTOT + kt + cc * 8;
            cpa16(uS + sb + 20480u + soff, g_BIh + gb);
            cpa16(uS + sb + 30720u + soff, g_BIm + gb);
        }
        asm volatile("cp.async.commit_group;" ::: "memory");
    };

    constexpr int NST = KTOT / 32;
    load_stage(0);
    load_stage(1);

#pragma unroll 1
    for (int s = 0; s < NST; s++) {
        if (s + 1 < NST)
            asm volatile("cp.async.wait_group 1;" ::: "memory");
        else
            asm volatile("cp.async.wait_group 0;" ::: "memory");
        __syncthreads();

        const int so4 = (s & 1) * 10240;             // stage offset in u32
#pragma unroll
        for (int ks = 0; ks < 2; ks++) {
            uint32_t Af[2][2][4];
#pragma unroll
            for (int v = 0; v < 2; v++)
#pragma unroll
                for (int mt = 0; mt < 2; mt++) {
                    int r0 = wm + mt * 16 + qr;
                    int base = so4 + v * 2560 + r0 * 20 + ks * 8 + qc;
                    Af[v][mt][0] = us[base];
                    Af[v][mt][1] = us[base + 160];
                    Af[v][mt][2] = us[base + 4];
                    Af[v][mt][3] = us[base + 164];
                }
#pragma unroll
            for (int nt = 0; nt < 8; nt++) {
                int n0 = wn + nt * 8 + qr;
                uint32_t Bf[2][2];
#pragma unroll
                for (int v = 0; v < 2; v++) {
                    int bb = so4 + (2 + v) * 2560 + n0 * 20 + ks * 8 + qc;
                    Bf[v][0] = us[bb];
                    Bf[v][1] = us[bb + 4];
                }
#pragma unroll
                for (int mt = 0; mt < 2; mt++) {
                    mma16(acc[mt][nt], Af[0][mt], Bf[0]);   // h*h
                    mma16(acc[mt][nt], Af[0][mt], Bf[1]);   // h*m
                    mma16(acc[mt][nt], Af[1][mt], Bf[0]);   // m*h
                }
            }
        }
        __syncthreads();
        if (s + 2 < NST) load_stage(s + 2);
    }

    const float sc = 2.0f / 1024.0f;
    float* __restrict__ Co = g_TD;
#pragma unroll
    for (int mt = 0; mt < 2; mt++)
#pragma unroll
        for (int nt = 0; nt < 8; nt++) {
            int rr = by * 128 + wm + mt * 16 + qr;
            int cb = bx * 128 + wn + nt * 8 + qc * 2;
            float2 v0 = make_float2(acc[mt][nt][0] * sc, acc[mt][nt][1] * sc);
            float2 v1 = make_float2(acc[mt][nt][2] * sc, acc[mt][nt][3] * sc);
            *(float2*)(Co + (size_t)rr * NC + cb)       = v0;
            *(float2*)(Co + (size_t)(rr + 8) * NC + cb) = v1;
        }
}
__global__ __launch_bounds__(256, 2) void k_bf_inv() { bf_inv(); }

// ---------------- per-(b,f) gain (round-10 version) -----------------------
__global__ void k_gain() {
    __shared__ int warpsum[8];
    __shared__ float s_lo, s_hi;
    const int bf   = blockIdx.x;
    const int tid  = threadIdx.x;
    const int lane = tid & 31, wid = tid >> 5;
    const float* cf = g_CO + (size_t)bf * 2048;

    float axr[8];
#pragma unroll
    for (int j = 0; j < 8; j++)
        axr[j] = powf(fabsf(cf[tid + j * 256]), 0.75f);

    if (tid == 0) { s_lo = 0.0f; s_hi = 120.0f; }
    __syncthreads();

    const float TARGET = (float)(128000.0 * 1024.0 / 48000.0);
#pragma unroll 1
    for (int it = 0; it < 8; it++) {
        float mid = floorf((s_lo + s_hi) * 0.5f);
        float inv = exp2f((-0.75f * mid) / 4.0f);
        int bits = 0;
#pragma unroll
        for (int j = 0; j < 8; j++) {
            int qi = (int)rintf(axr[j] * inv);
            bits += (qi > 0) ? (33 - __clz(qi)) : 1;
        }
#pragma unroll
        for (int o = 16; o > 0; o >>= 1)
            bits += __shfl_down_sync(0xffffffffu, bits, o);
        if (lane == 0) warpsum[wid] = bits;
        __syncthreads();
        if (tid == 0) {
            int tot = 0;
#pragma unroll
            for (int w = 0; w < 8; w++) tot += warpsum[w];
            if ((float)tot > TARGET) s_lo = mid + 1.0f;
            else                     s_hi = mid;
        }
        __syncthreads();
    }
    if (tid == 0) g_GA[bf] = s_hi;
}

// ---------------- quantize + dequantize + bf16 double split ---------------
__global__ void k_quant() {
    int idx = blockIdx.x * blockDim.x + threadIdx.x;
    if (idx >= Rv * Mv) return;
    int bf = idx >> 11;
    float g     = g_GA[bf];
    float scale = exp2f(g / 4.0f);
    float cv    = g_CO[idx];
    float s1 = (cv > 0.0f) ? 1.0f : ((cv < 0.0f) ? -1.0f : 0.0f);
    float qs = s1 * powf(fabsf(cv) / scale + 1e-9f, 0.75f);
    float q  = rintf(qs);
    float s2 = (q > 0.0f) ? 1.0f : ((q < 0.0f) ? -1.0f : 0.0f);
    float v  = s2 * powf(fabsf(q), (float)(4.0 / 3.0)) * scale;
    __nv_bfloat16 h, m;
    bsplit2(v, &h, &m);
    g_DQh[idx] = h; g_DQm[idx] = m;
}

// ---------------- window + overlap-add + crop ------------------------------
__global__ void k_ola(float* __restrict__ out) {
    int idx = blockIdx.x * blockDim.x + threadIdx.x;
    if (idx >= Bv * Cv * Tv) return;
    int t  = idx % Tv;
    int bc = idx / Tv;
    int b  = bc >> 1;
    int c  = bc & 1;
    int fb = t >> 10;
    int na = t & 1023;
    int rowa = (b * Fv + fb + 1) * Cv + c;
    int rowb = (b * Fv + fb) * Cv + c;
    float r1 = g_TD[(size_t)rowa * Nv + na]      * g_W[na];
    float r2 = g_TD[(size_t)rowb * Nv + na + Mv] * g_W[na + Mv];
    out[idx] = r1 + r2;
}

// ---------------- launch ----------------------------------------------------
extern "C" void kernel_launch(void* const* d_in, const int* in_sizes, int n_in,
                              void* d_out, int out_size) {
    const float* audio = (const float*)d_in[0];
    float* out = (float*)d_out;
    const int SMEM_BYTES = 2 * 40960;   // 81,920 B

    cudaFuncSetAttribute(k_bf_inv, cudaFuncAttributeMaxDynamicSharedMemorySize, SMEM_BYTES);

    k_tables<<<(Nv * Mv + 255) / 256, 256>>>();
    {
        long long tot = (long long)Rv * Nv;
        k_frames<<<(unsigned)((tot + 255) / 256), 256>>>(audio);
    }
    k_gemm_fwd<<<dim3(Mv / 128, Rv / 128), 256>>>();
    k_gain<<<NFRAME, 256>>>();
    k_quant<<<(Rv * Mv + 255) / 256, 256>>>();
    k_bf_inv<<<dim3(Nv / 128, Rv / 128), 256, SMEM_BYTES>>>();
    k_ola<<<(Bv * Cv * Tv + 255) / 256, 256>>>(out);
}

// round 16
// speedup vs baseline: 1.4315x; 1.0468x over previous
#include <cuda_runtime.h>
#include <cuda_bf16.h>
#include <math.h>
#include <stdint.h>

// ---------------- problem constants ----------------
#define Bv 8
#define Cv 2
#define Tv 1440000
#define Mv 1024
#define Nv 2048
#define Fv 1408
#define Rv (Bv*Fv*Cv)                // 22528 rows
#define NFRAME (Bv*Fv)               // 11264

// ---------------- static scratch ----------------
__device__ float g_W  [Nv];
__device__ float g_Cm [Nv*Mv];            // fwd B fp32: [n 2048][m 1024]
__device__ float g_FR [(size_t)Rv*Nv];    // fwd A fp32
__device__ float g_CO [(size_t)Rv*Mv];    // MDCT coeffs fp32
__device__ float g_TD [(size_t)Rv*Nv];    // inverse transform fp32
// bf16 double splits (inverse GEMM only; 3-term emulation)
__device__ __nv_bfloat16 g_DQh[(size_t)Rv*Mv], g_DQm[(size_t)Rv*Mv];
__device__ __nv_bfloat16 g_BIh[Nv*Mv], g_BIm[Nv*Mv];   // inv B [n][k=m]

// ---------------- helpers ----------------
__device__ __forceinline__ void bsplit2(float v, __nv_bfloat16* h, __nv_bfloat16* m) {
    __nv_bfloat16 hh = __float2bfloat16_rn(v);
    float r1 = v - __bfloat162float(hh);
    *h = hh; *m = __float2bfloat16_rn(r1);
}
__device__ __forceinline__ uint64_t splat2(float x) {
    uint64_t r; uint32_t u = __float_as_uint(x);
    asm("mov.b64 %0, {%1, %1};" : "=l"(r) : "r"(u));
    return r;
}
__device__ __forceinline__ void ffma2(uint64_t& d, uint64_t a, uint64_t b) {
    asm("fma.rn.f32x2 %0, %1, %2, %0;" : "+l"(d) : "l"(a), "l"(b));
}
__device__ __forceinline__ void fadd2(uint64_t& d, uint64_t a) {
    asm("add.rn.f32x2 %0, %0, %1;" : "+l"(d) : "l"(a));
}
__device__ __forceinline__ float lo32(uint64_t v) {
    return __uint_as_float((uint32_t)(v & 0xffffffffu));
}
__device__ __forceinline__ float hi32(uint64_t v) {
    return __uint_as_float((uint32_t)(v >> 32));
}
__device__ __forceinline__ void mma16(float* d, const uint32_t* a, const uint32_t* b) {
    asm volatile(
        "mma.sync.aligned.m16n8k16.row.col.f32.bf16.bf16.f32 "
        "{%0,%1,%2,%3}, {%4,%5,%6,%7}, {%8,%9}, {%0,%1,%2,%3};"
        : "+f"(d[0]), "+f"(d[1]), "+f"(d[2]), "+f"(d[3])
        : "r"(a[0]), "r"(a[1]), "r"(a[2]), "r"(a[3]), "r"(b[0]), "r"(b[1]));
}
__device__ __forceinline__ void cpa16(uint32_t saddr, const void* g) {
    asm volatile("cp.async.cg.shared.global [%0], [%1], 16;"
                 :: "r"(saddr), "l"(g) : "memory");
}

// ---------------- tables: identical cos numerics to round 3 --------------
__global__ void k_tables() {
    int idx = blockIdx.x * blockDim.x + threadIdx.x;
    if (idx >= Nv * Mv) return;
    int n = idx >> 10;
    int k = idx & 1023;
    const float c0 = (float)(3.14159265358979323846 / 1024.0);
    float a   = c0 * ((float)n + 512.5f);
    float arg = a * ((float)k + 0.5f);
    float v   = cosf(arg);
    g_Cm[n * Mv + k] = v;                       // fwd B fp32 [n][m]
    __nv_bfloat16 h, m;
    bsplit2(v, &h, &m);
    g_BIh[n * Mv + k] = h;                      // inv B [n][k=m]
    g_BIm[n * Mv + k] = m;
    if (idx < Nv) {
        const float c1 = (float)(3.14159265358979323846 / 2048.0);
        g_W[idx] = sinf(c1 * ((float)idx + 0.5f));
    }
}

// ---------------- frame + window (float4 vectorized) ----------------------
__global__ void k_frames(const float* __restrict__ audio) {
    long long vid = (long long)blockIdx.x * blockDim.x + threadIdx.x;
    long long base = vid * 4;
    if (base >= (long long)Rv * Nv) return;
    int n   = (int)(base & (Nv - 1));          // n % 4 == 0
    int row = (int)(base >> 11);
    int c   = row & 1;
    int bf  = row >> 1;
    int f   = bf % Fv;
    int b   = bf / Fv;
    int src = f * Mv + n - Mv;
    const float* ap = audio + (size_t)(b * Cv + c) * Tv;
    float4 x;
    if (src >= 0 && src + 3 < Tv) {
        x = *(const float4*)(ap + src);        // src % 4 == 0
    } else {
        x.x = (src     >= 0 && src     < Tv) ? ap[src]     : 0.0f;
        x.y = (src + 1 >= 0 && src + 1 < Tv) ? ap[src + 1] : 0.0f;
        x.z = (src + 2 >= 0 && src + 2 < Tv) ? ap[src + 2] : 0.0f;
        x.w = (src + 3 >= 0 && src + 3 < Tv) ? ap[src + 3] : 0.0f;
    }
    float4 w = *(const float4*)(g_W + n);
    float4 o;
    o.x = x.x * w.x; o.y = x.y * w.y; o.z = x.z * w.z; o.w = x.w * w.w;
    *(float4*)(g_FR + base) = o;
}

// ---------------- fwd GEMM: round-13 f32x2 FFMA kernel (bit-frozen) -------
// 256 threads, 8x8 thread tiles, BK=8 double-buffered. DO NOT ALTER:
// coefficients must stay bit-identical (gain search sits on integer edges).
__device__ __forceinline__ void sgemm_fwd() {
    const float* __restrict__ A = g_FR;
    const float* __restrict__ B = g_Cm;
    float* __restrict__ Co = g_CO;
    constexpr int K = Nv, NC = Mv;
    __shared__ float As[2][8][128];
    __shared__ float Bs[2][8][128];
    const int tid  = threadIdx.x;
    const int bx   = blockIdx.x;
    const int by   = blockIdx.y;
    const int arow = tid >> 1;
    const int acol = (tid & 1) << 2;
    const int brow = tid >> 5;
    const int bcol = (tid & 31) << 2;
    const int tx   = tid & 15;
    const int ty   = tid >> 4;

    const float* Ap = A + (size_t)(by * 128 + arow) * K + acol;
    const float* Bp = B + (size_t)brow * NC + bx * 128 + bcol;

    uint64_t accT[4][8], accC[4][8];
#pragma unroll
    for (int i = 0; i < 4; i++)
#pragma unroll
        for (int j = 0; j < 8; j++) { accT[i][j] = 0ull; accC[i][j] = 0ull; }

    {
        float4 a4 = *(const float4*)Ap;
        float4 b4 = *(const float4*)Bp;
        As[0][acol + 0][arow] = a4.x;
        As[0][acol + 1][arow] = a4.y;
        As[0][acol + 2][arow] = a4.z;
        As[0][acol + 3][arow] = a4.w;
        *(float4*)&Bs[0][brow][bcol] = b4;
    }
    __syncthreads();

    const int NT = K / 8;
    int buf = 0;
#pragma unroll 1
    for (int t = 0; t < NT; ++t) {
        float4 na, nb4;
        const bool have_next = (t + 1 < NT);
        if (have_next) {
            na  = *(const float4*)(Ap + (size_t)(t + 1) * 8);
            nb4 = *(const float4*)(Bp + (size_t)(t + 1) * 8 * NC);
        }
#pragma unroll
        for (int k = 0; k < 8; k++) {
            uint64_t ap[4];
            {
                const ulonglong2* p2 = (const ulonglong2*)&As[buf][k][ty * 8];
                ulonglong2 v0 = p2[0], v1 = p2[1];
                ap[0] = v0.x; ap[1] = v0.y; ap[2] = v1.x; ap[3] = v1.y;
            }
            float rb[8];
            *(float4*)&rb[0] = *(const float4*)&Bs[buf][k][tx * 8];
            *(float4*)&rb[4] = *(const float4*)&Bs[buf][k][tx * 8 + 4];
            uint64_t bs[8];
#pragma unroll
            for (int j = 0; j < 8; j++) bs[j] = splat2(rb[j]);
#pragma unroll
            for (int i = 0; i < 4; i++)
#pragma unroll
                for (int j = 0; j < 8; j++)
                    ffma2(accC[i][j], ap[i], bs[j]);
        }
        if (((t + 1) & 31) == 0) {
#pragma unroll
            for (int i = 0; i < 4; i++)
#pragma unroll
                for (int j = 0; j < 8; j++) {
                    fadd2(accT[i][j], accC[i][j]);
                    accC[i][j] = 0ull;
                }
        }
        if (have_next) {
            int nbuf = buf ^ 1;
            As[nbuf][acol + 0][arow] = na.x;
            As[nbuf][acol + 1][arow] = na.y;
            As[nbuf][acol + 2][arow] = na.z;
            As[nbuf][acol + 3][arow] = na.w;
            *(float4*)&Bs[nbuf][brow][bcol] = nb4;
            __syncthreads();
            buf = nbuf;
        }
    }

    float* Cp = Co + (size_t)(by * 128 + ty * 8) * NC + bx * 128 + tx * 8;
#pragma unroll
    for (int i = 0; i < 8; i++) {
        const int i2 = i >> 1;
        float4 o0, o1;
        if ((i & 1) == 0) {
            o0.x = lo32(accT[i2][0]); o0.y = lo32(accT[i2][1]);
            o0.z = lo32(accT[i2][2]); o0.w = lo32(accT[i2][3]);
            o1.x = lo32(accT[i2][4]); o1.y = lo32(accT[i2][5]);
            o1.z = lo32(accT[i2][6]); o1.w = lo32(accT[i2][7]);
        } else {
            o0.x = hi32(accT[i2][0]); o0.y = hi32(accT[i2][1]);
            o0.z = hi32(accT[i2][2]); o0.w = hi32(accT[i2][3]);
            o1.x = hi32(accT[i2][4]); o1.y = hi32(accT[i2][5]);
            o1.z = hi32(accT[i2][6]); o1.w = hi32(accT[i2][7]);
        }
        *(float4*)(Cp + (size_t)i * NC)     = o0;
        *(float4*)(Cp + (size_t)i * NC + 4) = o1;
    }
}
__global__ __launch_bounds__(256, 1) void k_gemm_fwd() { sgemm_fwd(); }

// ---------------- inv GEMM: bf16x2 (3-term) mma, BK=32, 2-stage -----------
__device__ __forceinline__ void bf_inv() {
    constexpr int KTOT = Mv, NC = Nv;
    extern __shared__ char sm[];
    const uint32_t uS = (uint32_t)__cvta_generic_to_shared(sm);
    const uint32_t* us = (const uint32_t*)sm;

    const int tid  = threadIdx.x;
    const int bx   = blockIdx.x, by = blockIdx.y;
    const int lane = tid & 31, wid = tid >> 5;
    const int wm   = (wid & 3) * 32;
    const int wn   = (wid >> 2) * 64;
    const int qr   = lane >> 2, qc = lane & 3;

    float acc[2][8][4];
#pragma unroll
    for (int i = 0; i < 2; i++)
#pragma unroll
        for (int j = 0; j < 8; j++)
#pragma unroll
            for (int c = 0; c < 4; c++) acc[i][j][c] = 0.0f;

    auto load_stage = [&](int s) {
        const uint32_t sb = (uint32_t)(s & 1) * 40960u;
        const int kt = s * 32;
#pragma unroll
        for (int i = 0; i < 2; i++) {
            const int idx = tid + i * 256;           // all 128 rows
            const int r  = idx >> 2;
            const int cc = idx & 3;
            const uint32_t soff = (uint32_t)(r * 80 + cc * 16);
            size_t ga = (size_t)(by * 128 + r) * KTOT + kt + cc * 8;
            cpa16(uS + sb +     0u + soff, g_DQh + ga);
            cpa16(uS + sb + 10240u + soff, g_DQm + ga);
            size_t gb = (size_t)(bx * 128 + r) * KTOT + kt + cc * 8;
            cpa16(uS + sb + 20480u + soff, g_BIh + gb);
            cpa16(uS + sb + 30720u + soff, g_BIm + gb);
        }
        asm volatile("cp.async.commit_group;" ::: "memory");
    };

    constexpr int NST = KTOT / 32;
    load_stage(0);
    load_stage(1);

#pragma unroll 1
    for (int s = 0; s < NST; s++) {
        if (s + 1 < NST)
            asm volatile("cp.async.wait_group 1;" ::: "memory");
        else
            asm volatile("cp.async.wait_group 0;" ::: "memory");
        __syncthreads();

        const int so4 = (s & 1) * 10240;             // stage offset in u32
#pragma unroll
        for (int ks = 0; ks < 2; ks++) {
            uint32_t Af[2][2][4];
#pragma unroll
            for (int v = 0; v < 2; v++)
#pragma unroll
                for (int mt = 0; mt < 2; mt++) {
                    int r0 = wm + mt * 16 + qr;
                    int base = so4 + v * 2560 + r0 * 20 + ks * 8 + qc;
                    Af[v][mt][0] = us[base];
                    Af[v][mt][1] = us[base + 160];
                    Af[v][mt][2] = us[base + 4];
                    Af[v][mt][3] = us[base + 164];
                }
#pragma unroll
            for (int nt = 0; nt < 8; nt++) {
                int n0 = wn + nt * 8 + qr;
                uint32_t Bf[2][2];
#pragma unroll
                for (int v = 0; v < 2; v++) {
                    int bb = so4 + (2 + v) * 2560 + n0 * 20 + ks * 8 + qc;
                    Bf[v][0] = us[bb];
                    Bf[v][1] = us[bb + 4];
                }
#pragma unroll
                for (int mt = 0; mt < 2; mt++) {
                    mma16(acc[mt][nt], Af[0][mt], Bf[0]);   // h*h
                    mma16(acc[mt][nt], Af[0][mt], Bf[1]);   // h*m
                    mma16(acc[mt][nt], Af[1][mt], Bf[0]);   // m*h
                }
            }
        }
        __syncthreads();
        if (s + 2 < NST) load_stage(s + 2);
    }

    const float sc = 2.0f / 1024.0f;
    float* __restrict__ Co = g_TD;
#pragma unroll
    for (int mt = 0; mt < 2; mt++)
#pragma unroll
        for (int nt = 0; nt < 8; nt++) {
            int rr = by * 128 + wm + mt * 16 + qr;
            int cb = bx * 128 + wn + nt * 8 + qc * 2;
            float2 v0 = make_float2(acc[mt][nt][0] * sc, acc[mt][nt][1] * sc);
            float2 v1 = make_float2(acc[mt][nt][2] * sc, acc[mt][nt][3] * sc);
            *(float2*)(Co + (size_t)rr * NC + cb)       = v0;
            *(float2*)(Co + (size_t)(rr + 8) * NC + cb) = v1;
        }
}
__global__ __launch_bounds__(256, 2) void k_bf_inv() { bf_inv(); }

// ---------------- fused gain search + quantize/dequantize -----------------
// Gain loop is BIT-IDENTICAL to round 10/15 (untouched). After convergence,
// each thread quantizes its 8 register-held coefficients (exact reference
// expression) and writes the bf16 splits for the inverse GEMM.
__global__ void k_gain_quant() {
    __shared__ int warpsum[8];
    __shared__ float s_lo, s_hi;
    const int bf   = blockIdx.x;
    const int tid  = threadIdx.x;
    const int lane = tid & 31, wid = tid >> 5;
    const float* cf = g_CO + (size_t)bf * 2048;

    float cvr[8], axr[8];
#pragma unroll
    for (int j = 0; j < 8; j++) {
        cvr[j] = cf[tid + j * 256];
        axr[j] = powf(fabsf(cvr[j]), 0.75f);
    }

    if (tid == 0) { s_lo = 0.0f; s_hi = 120.0f; }
    __syncthreads();

    const float TARGET = (float)(128000.0 * 1024.0 / 48000.0);
#pragma unroll 1
    for (int it = 0; it < 8; it++) {
        float mid = floorf((s_lo + s_hi) * 0.5f);
        float inv = exp2f((-0.75f * mid) / 4.0f);
        int bits = 0;
#pragma unroll
        for (int j = 0; j < 8; j++) {
            int qi = (int)rintf(axr[j] * inv);
            bits += (qi > 0) ? (33 - __clz(qi)) : 1;
        }
#pragma unroll
        for (int o = 16; o > 0; o >>= 1)
            bits += __shfl_down_sync(0xffffffffu, bits, o);
        if (lane == 0) warpsum[wid] = bits;
        __syncthreads();
        if (tid == 0) {
            int tot = 0;
#pragma unroll
            for (int w = 0; w < 8; w++) tot += warpsum[w];
            if ((float)tot > TARGET) s_lo = mid + 1.0f;
            else                     s_hi = mid;
        }
        __syncthreads();
    }

    const float g = s_hi;
    const float scale = exp2f(g / 4.0f);
    __nv_bfloat16* dh = g_DQh + (size_t)bf * 2048;
    __nv_bfloat16* dm = g_DQm + (size_t)bf * 2048;
#pragma unroll
    for (int j = 0; j < 8; j++) {
        float cv = cvr[j];
        float s1 = (cv > 0.0f) ? 1.0f : ((cv < 0.0f) ? -1.0f : 0.0f);
        float qs = s1 * powf(fabsf(cv) / scale + 1e-9f, 0.75f);
        float q  = rintf(qs);
        float s2 = (q > 0.0f) ? 1.0f : ((q < 0.0f) ? -1.0f : 0.0f);
        float v  = s2 * powf(fabsf(q), (float)(4.0 / 3.0)) * scale;
        __nv_bfloat16 h, m;
        bsplit2(v, &h, &m);
        dh[tid + j * 256] = h;
        dm[tid + j * 256] = m;
    }
}

// ---------------- window + overlap-add + crop (float4) --------------------
__global__ void k_ola(float* __restrict__ out) {
    int vid = blockIdx.x * blockDim.x + threadIdx.x;
    long long base = (long long)vid * 4;
    if (base >= (long long)Bv * Cv * Tv) return;
    int t  = (int)(base % Tv);                 // Tv % 4 == 0 -> t % 4 == 0
    int bc = (int)(base / Tv);
    int b  = bc >> 1;
    int c  = bc & 1;
    int fb = t >> 10;                          // same for t..t+3 (na%4==0)
    int na = t & 1023;
    int rowa = (b * Fv + fb + 1) * Cv + c;
    int rowb = (b * Fv + fb) * Cv + c;
    float4 r1 = *(const float4*)(g_TD + (size_t)rowa * Nv + na);
    float4 r2 = *(const float4*)(g_TD + (size_t)rowb * Nv + na + Mv);
    float4 w1 = *(const float4*)(g_W + na);
    float4 w2 = *(const float4*)(g_W + na + Mv);
    float4 o;
    o.x = r1.x * w1.x + r2.x * w2.x;
    o.y = r1.y * w1.y + r2.y * w2.y;
    o.z = r1.z * w1.z + r2.z * w2.z;
    o.w = r1.w * w1.w + r2.w * w2.w;
    *(float4*)(out + base) = o;
}

// ---------------- launch ----------------------------------------------------
extern "C" void kernel_launch(void* const* d_in, const int* in_sizes, int n_in,
                              void* d_out, int out_size) {
    const float* audio = (const float*)d_in[0];
    float* out = (float*)d_out;
    const int SMEM_BYTES = 2 * 40960;   // 81,920 B

    cudaFuncSetAttribute(k_bf_inv, cudaFuncAttributeMaxDynamicSharedMemorySize, SMEM_BYTES);

    k_tables<<<(Nv * Mv + 255) / 256, 256>>>();
    {
        long long tot = (long long)Rv * Nv / 4;
        k_frames<<<(unsigned)((tot + 255) / 256), 256>>>(audio);
    }
    k_gemm_fwd<<<dim3(Mv / 128, Rv / 128), 256>>>();
    k_gain_quant<<<NFRAME, 256>>>();
    k_bf_inv<<<dim3(Nv / 128, Rv / 128), 256, SMEM_BYTES>>>();
    {
        int tot = Bv * Cv * Tv / 4;
        k_ola<<<(tot + 255) / 256, 256>>>(out);
    }
}

// round 17
// speedup vs baseline: 1.4705x; 1.0272x over previous
#include <cuda_runtime.h>
#include <cuda_bf16.h>
#include <math.h>
#include <stdint.h>

// ---------------- problem constants ----------------
#define Bv 8
#define Cv 2
#define Tv 1440000
#define Mv 1024
#define Nv 2048
#define Fv 1408
#define Rv (Bv*Fv*Cv)                // 22528 rows
#define NFRAME (Bv*Fv)               // 11264

// ---------------- static scratch ----------------
__device__ float g_W  [Nv];
__device__ float g_Cm [Nv*Mv];            // fwd B fp32: [n 2048][m 1024]
__device__ float g_FR [(size_t)Rv*Nv];    // fwd A fp32
__device__ float g_CO [(size_t)Rv*Mv];    // MDCT coeffs fp32
__device__ float g_TD [(size_t)Rv*Nv];    // inverse transform fp32
// bf16 double splits (inverse GEMM only; 3-term emulation)
__device__ __nv_bfloat16 g_DQh[(size_t)Rv*Mv], g_DQm[(size_t)Rv*Mv];
__device__ __nv_bfloat16 g_BIh[Nv*Mv], g_BIm[Nv*Mv];   // inv B [n][k=m]

// ---------------- helpers ----------------
__device__ __forceinline__ void bsplit2(float v, __nv_bfloat16* h, __nv_bfloat16* m) {
    __nv_bfloat16 hh = __float2bfloat16_rn(v);
    float r1 = v - __bfloat162float(hh);
    *h = hh; *m = __float2bfloat16_rn(r1);
}
__device__ __forceinline__ uint64_t splat2(float x) {
    uint64_t r; uint32_t u = __float_as_uint(x);
    asm("mov.b64 %0, {%1, %1};" : "=l"(r) : "r"(u));
    return r;
}
__device__ __forceinline__ void ffma2(uint64_t& d, uint64_t a, uint64_t b) {
    asm("fma.rn.f32x2 %0, %1, %2, %0;" : "+l"(d) : "l"(a), "l"(b));
}
__device__ __forceinline__ void fadd2(uint64_t& d, uint64_t a) {
    asm("add.rn.f32x2 %0, %0, %1;" : "+l"(d) : "l"(a));
}
__device__ __forceinline__ float lo32(uint64_t v) {
    return __uint_as_float((uint32_t)(v & 0xffffffffu));
}
__device__ __forceinline__ float hi32(uint64_t v) {
    return __uint_as_float((uint32_t)(v >> 32));
}
__device__ __forceinline__ void mma16(float* d, const uint32_t* a, const uint32_t* b) {
    asm volatile(
        "mma.sync.aligned.m16n8k16.row.col.f32.bf16.bf16.f32 "
        "{%0,%1,%2,%3}, {%4,%5,%6,%7}, {%8,%9}, {%0,%1,%2,%3};"
        : "+f"(d[0]), "+f"(d[1]), "+f"(d[2]), "+f"(d[3])
        : "r"(a[0]), "r"(a[1]), "r"(a[2]), "r"(a[3]), "r"(b[0]), "r"(b[1]));
}
__device__ __forceinline__ void cpa16(uint32_t saddr, const void* g) {
    asm volatile("cp.async.cg.shared.global [%0], [%1], 16;"
                 :: "r"(saddr), "l"(g) : "memory");
}

// ---------------- tables: identical cos numerics to round 3 --------------
__global__ void k_tables() {
    int idx = blockIdx.x * blockDim.x + threadIdx.x;
    if (idx >= Nv * Mv) return;
    int n = idx >> 10;
    int k = idx & 1023;
    const float c0 = (float)(3.14159265358979323846 / 1024.0);
    float a   = c0 * ((float)n + 512.5f);
    float arg = a * ((float)k + 0.5f);
    float v   = cosf(arg);
    g_Cm[n * Mv + k] = v;                       // fwd B fp32 [n][m]
    __nv_bfloat16 h, m;
    bsplit2(v, &h, &m);
    g_BIh[n * Mv + k] = h;                      // inv B [n][k=m]
    g_BIm[n * Mv + k] = m;
    if (idx < Nv) {
        const float c1 = (float)(3.14159265358979323846 / 2048.0);
        g_W[idx] = sinf(c1 * ((float)idx + 0.5f));
    }
}

// ---------------- frame + window (float4 vectorized) ----------------------
__global__ void k_frames(const float* __restrict__ audio) {
    long long vid = (long long)blockIdx.x * blockDim.x + threadIdx.x;
    long long base = vid * 4;
    if (base >= (long long)Rv * Nv) return;
    int n   = (int)(base & (Nv - 1));          // n % 4 == 0
    int row = (int)(base >> 11);
    int c   = row & 1;
    int bf  = row >> 1;
    int f   = bf % Fv;
    int b   = bf / Fv;
    int src = f * Mv + n - Mv;
    const float* ap = audio + (size_t)(b * Cv + c) * Tv;
    float4 x;
    if (src >= 0 && src + 3 < Tv) {
        x = *(const float4*)(ap + src);        // src % 4 == 0
    } else {
        x.x = (src     >= 0 && src     < Tv) ? ap[src]     : 0.0f;
        x.y = (src + 1 >= 0 && src + 1 < Tv) ? ap[src + 1] : 0.0f;
        x.z = (src + 2 >= 0 && src + 2 < Tv) ? ap[src + 2] : 0.0f;
        x.w = (src + 3 >= 0 && src + 3 < Tv) ? ap[src + 3] : 0.0f;
    }
    float4 w = *(const float4*)(g_W + n);
    float4 o;
    o.x = x.x * w.x; o.y = x.y * w.y; o.z = x.z * w.z; o.w = x.w * w.w;
    *(float4*)(g_FR + base) = o;
}

// ---------------- fwd GEMM v3: 64x128 CTA tile, 128 threads ---------------
// Per-thread tile stays 8x8 (same FLOP/LDS ratio as the green round-13/16
// kernel). Same k order (0..2047), same fold-every-256, same even/odd FFMA2
// lane pairing of adjacent global rows => BIT-IDENTICAL coefficients.
// 128 threads x ~170 regs => 3 CTAs/SM (vs 1), +50% warps/SMSP.
__device__ __forceinline__ void sgemm_fwd() {
    const float* __restrict__ A = g_FR;
    const float* __restrict__ B = g_Cm;
    float* __restrict__ Co = g_CO;
    constexpr int K = Nv, NC = Mv;
    __shared__ float As[2][8][64];
    __shared__ float Bs[2][8][128];
    const int tid  = threadIdx.x;            // 0..127
    const int bx   = blockIdx.x;             // 8 tiles of 128 cols
    const int by   = blockIdx.y;             // 352 tiles of 64 rows
    const int arow = tid >> 1;               // 0..63
    const int acol = (tid & 1) << 2;         // 0,4
    const int tx   = tid & 15;               // col group (8 cols)
    const int ty   = tid >> 4;               // 0..7, row group (8 rows)

    const float* Ap = A + (size_t)(by * 64 + arow) * K + acol;

    uint64_t accT[4][8], accC[4][8];
#pragma unroll
    for (int i = 0; i < 4; i++)
#pragma unroll
        for (int j = 0; j < 8; j++) { accT[i][j] = 0ull; accC[i][j] = 0ull; }

    {   // prologue: tile 0
        float4 a4 = *(const float4*)Ap;
        As[0][acol + 0][arow] = a4.x;
        As[0][acol + 1][arow] = a4.y;
        As[0][acol + 2][arow] = a4.z;
        As[0][acol + 3][arow] = a4.w;
#pragma unroll
        for (int it = 0; it < 2; it++) {
            int idx  = tid + it * 128;           // 0..255
            int brow = idx >> 5;                 // 0..7
            int bcol = (idx & 31) << 2;          // 0..124
            *(float4*)&Bs[0][brow][bcol] =
                *(const float4*)(B + (size_t)brow * NC + bx * 128 + bcol);
        }
    }
    __syncthreads();

    const int NT = K / 8;
    int buf = 0;
#pragma unroll 1
    for (int t = 0; t < NT; ++t) {
        float4 na, nb0, nb1;
        const bool have_next = (t + 1 < NT);
        int brow0, bcol0, brow1, bcol1;
        if (have_next) {
            na = *(const float4*)(Ap + (size_t)(t + 1) * 8);
            int idx0 = tid;
            brow0 = idx0 >> 5; bcol0 = (idx0 & 31) << 2;
            nb0 = *(const float4*)(B + (size_t)((t + 1) * 8 + brow0) * NC
                                     + bx * 128 + bcol0);
            int idx1 = tid + 128;
            brow1 = idx1 >> 5; bcol1 = (idx1 & 31) << 2;
            nb1 = *(const float4*)(B + (size_t)((t + 1) * 8 + brow1) * NC
                                     + bx * 128 + bcol1);
        }
#pragma unroll
        for (int k = 0; k < 8; k++) {
            uint64_t ap[4];
            {
                const ulonglong2* p2 = (const ulonglong2*)&As[buf][k][ty * 8];
                ulonglong2 v0 = p2[0], v1 = p2[1];
                ap[0] = v0.x; ap[1] = v0.y; ap[2] = v1.x; ap[3] = v1.y;
            }
            float rb[8];
            *(float4*)&rb[0] = *(const float4*)&Bs[buf][k][tx * 8];
            *(float4*)&rb[4] = *(const float4*)&Bs[buf][k][tx * 8 + 4];
            uint64_t bs[8];
#pragma unroll
            for (int j = 0; j < 8; j++) bs[j] = splat2(rb[j]);
#pragma unroll
            for (int i = 0; i < 4; i++)
#pragma unroll
                for (int j = 0; j < 8; j++)
                    ffma2(accC[i][j], ap[i], bs[j]);
        }
        if (((t + 1) & 31) == 0) {               // fold every 256 k
#pragma unroll
            for (int i = 0; i < 4; i++)
#pragma unroll
                for (int j = 0; j < 8; j++) {
                    fadd2(accT[i][j], accC[i][j]);
                    accC[i][j] = 0ull;
                }
        }
        if (have_next) {
            int nbuf = buf ^ 1;
            As[nbuf][acol + 0][arow] = na.x;
            As[nbuf][acol + 1][arow] = na.y;
            As[nbuf][acol + 2][arow] = na.z;
            As[nbuf][acol + 3][arow] = na.w;
            *(float4*)&Bs[nbuf][brow0][bcol0] = nb0;
            *(float4*)&Bs[nbuf][brow1][bcol1] = nb1;
            __syncthreads();
            buf = nbuf;
        }
    }

    float* Cp = Co + (size_t)(by * 64 + ty * 8) * NC + bx * 128 + tx * 8;
#pragma unroll
    for (int i = 0; i < 8; i++) {
        const int i2 = i >> 1;
        float4 o0, o1;
        if ((i & 1) == 0) {
            o0.x = lo32(accT[i2][0]); o0.y = lo32(accT[i2][1]);
            o0.z = lo32(accT[i2][2]); o0.w = lo32(accT[i2][3]);
            o1.x = lo32(accT[i2][4]); o1.y = lo32(accT[i2][5]);
            o1.z = lo32(accT[i2][6]); o1.w = lo32(accT[i2][7]);
        } else {
            o0.x = hi32(accT[i2][0]); o0.y = hi32(accT[i2][1]);
            o0.z = hi32(accT[i2][2]); o0.w = hi32(accT[i2][3]);
            o1.x = hi32(accT[i2][4]); o1.y = hi32(accT[i2][5]);
            o1.z = hi32(accT[i2][6]); o1.w = hi32(accT[i2][7]);
        }
        *(float4*)(Cp + (size_t)i * NC)     = o0;
        *(float4*)(Cp + (size_t)i * NC + 4) = o1;
    }
}
__global__ __launch_bounds__(128) void k_gemm_fwd() { sgemm_fwd(); }

// ---------------- inv GEMM: bf16x2 (3-term) mma, BK=32, 2-stage -----------
__device__ __forceinline__ void bf_inv() {
    constexpr int KTOT = Mv, NC = Nv;
    extern __shared__ char sm[];
    const uint32_t uS = (uint32_t)__cvta_generic_to_shared(sm);
    const uint32_t* us = (const uint32_t*)sm;

    const int tid  = threadIdx.x;
    const int bx   = blockIdx.x, by = blockIdx.y;
    const int lane = tid & 31, wid = tid >> 5;
    const int wm   = (wid & 3) * 32;
    const int wn   = (wid >> 2) * 64;
    const int qr   = lane >> 2, qc = lane & 3;

    float acc[2][8][4];
#pragma unroll
    for (int i = 0; i < 2; i++)
#pragma unroll
        for (int j = 0; j < 8; j++)
#pragma unroll
            for (int c = 0; c < 4; c++) acc[i][j][c] = 0.0f;

    auto load_stage = [&](int s) {
        const uint32_t sb = (uint32_t)(s & 1) * 40960u;
        const int kt = s * 32;
#pragma unroll
        for (int i = 0; i < 2; i++) {
            const int idx = tid + i * 256;           // all 128 rows
            const int r  = idx >> 2;
            const int cc = idx & 3;
            const uint32_t soff = (uint32_t)(r * 80 + cc * 16);
            size_t ga = (size_t)(by * 128 + r) * KTOT + kt + cc * 8;
            cpa16(uS + sb +     0u + soff, g_DQh + ga);
            cpa16(uS + sb + 10240u + soff, g_DQm + ga);
            size_t gb = (size_t)(bx * 128 + r) * KTOT + kt + cc * 8;
            cpa16(uS + sb + 20480u + soff, g_BIh + gb);
            cpa16(uS + sb + 30720u + soff, g_BIm + gb);
        }
        asm volatile("cp.async.commit_group;" ::: "memory");
    };

    constexpr int NST = KTOT / 32;
    load_stage(0);
    load_stage(1);

#pragma unroll 1
    for (int s = 0; s < NST; s++) {
        if (s + 1 < NST)
            asm volatile("cp.async.wait_group 1;" ::: "memory");
        else
            asm volatile("cp.async.wait_group 0;" ::: "memory");
        __syncthreads();

        const int so4 = (s & 1) * 10240;             // stage offset in u32
#pragma unroll
        for (int ks = 0; ks < 2; ks++) {
            uint32_t Af[2][2][4];
#pragma unroll
            for (int v = 0; v < 2; v++)
#pragma unroll
                for (int mt = 0; mt < 2; mt++) {
                    int r0 = wm + mt * 16 + qr;
                    int base = so4 + v * 2560 + r0 * 20 + ks * 8 + qc;
                    Af[v][mt][0] = us[base];
                    Af[v][mt][1] = us[base + 160];
                    Af[v][mt][2] = us[base + 4];
                    Af[v][mt][3] = us[base + 164];
                }
#pragma unroll
            for (int nt = 0; nt < 8; nt++) {
                int n0 = wn + nt * 8 + qr;
                uint32_t Bf[2][2];
#pragma unroll
                for (int v = 0; v < 2; v++) {
                    int bb = so4 + (2 + v) * 2560 + n0 * 20 + ks * 8 + qc;
                    Bf[v][0] = us[bb];
                    Bf[v][1] = us[bb + 4];
                }
#pragma unroll
                for (int mt = 0; mt < 2; mt++) {
                    mma16(acc[mt][nt], Af[0][mt], Bf[0]);   // h*h
                    mma16(acc[mt][nt], Af[0][mt], Bf[1]);   // h*m
                    mma16(acc[mt][nt], Af[1][mt], Bf[0]);   // m*h
                }
            }
        }
        __syncthreads();
        if (s + 2 < NST) load_stage(s + 2);
    }

    const float sc = 2.0f / 1024.0f;
    float* __restrict__ Co = g_TD;
#pragma unroll
    for (int mt = 0; mt < 2; mt++)
#pragma unroll
        for (int nt = 0; nt < 8; nt++) {
            int rr = by * 128 + wm + mt * 16 + qr;
            int cb = bx * 128 + wn + nt * 8 + qc * 2;
            float2 v0 = make_float2(acc[mt][nt][0] * sc, acc[mt][nt][1] * sc);
            float2 v1 = make_float2(acc[mt][nt][2] * sc, acc[mt][nt][3] * sc);
            *(float2*)(Co + (size_t)rr * NC + cb)       = v0;
            *(float2*)(Co + (size_t)(rr + 8) * NC + cb) = v1;
        }
}
__global__ __launch_bounds__(256, 2) void k_bf_inv() { bf_inv(); }

// ---------------- fused gain search + quantize/dequantize -----------------
// Gain loop BIT-IDENTICAL to rounds 10/15/16.
__global__ void k_gain_quant() {
    __shared__ int warpsum[8];
    __shared__ float s_lo, s_hi;
    const int bf   = blockIdx.x;
    const int tid  = threadIdx.x;
    const int lane = tid & 31, wid = tid >> 5;
    const float* cf = g_CO + (size_t)bf * 2048;

    float cvr[8], axr[8];
#pragma unroll
    for (int j = 0; j < 8; j++) {
        cvr[j] = cf[tid + j * 256];
        axr[j] = powf(fabsf(cvr[j]), 0.75f);
    }

    if (tid == 0) { s_lo = 0.0f; s_hi = 120.0f; }
    __syncthreads();

    const float TARGET = (float)(128000.0 * 1024.0 / 48000.0);
#pragma unroll 1
    for (int it = 0; it < 8; it++) {
        float mid = floorf((s_lo + s_hi) * 0.5f);
        float inv = exp2f((-0.75f * mid) / 4.0f);
        int bits = 0;
#pragma unroll
        for (int j = 0; j < 8; j++) {
            int qi = (int)rintf(axr[j] * inv);
            bits += (qi > 0) ? (33 - __clz(qi)) : 1;
        }
#pragma unroll
        for (int o = 16; o > 0; o >>= 1)
            bits += __shfl_down_sync(0xffffffffu, bits, o);
        if (lane == 0) warpsum[wid] = bits;
        __syncthreads();
        if (tid == 0) {
            int tot = 0;
#pragma unroll
            for (int w = 0; w < 8; w++) tot += warpsum[w];
            if ((float)tot > TARGET) s_lo = mid + 1.0f;
            else                     s_hi = mid;
        }
        __syncthreads();
    }

    const float g = s_hi;
    const float scale = exp2f(g / 4.0f);
    __nv_bfloat16* dh = g_DQh + (size_t)bf * 2048;
    __nv_bfloat16* dm = g_DQm + (size_t)bf * 2048;
#pragma unroll
    for (int j = 0; j < 8; j++) {
        float cv = cvr[j];
        float s1 = (cv > 0.0f) ? 1.0f : ((cv < 0.0f) ? -1.0f : 0.0f);
        float qs = s1 * powf(fabsf(cv) / scale + 1e-9f, 0.75f);
        float q  = rintf(qs);
        float s2 = (q > 0.0f) ? 1.0f : ((q < 0.0f) ? -1.0f : 0.0f);
        float v  = s2 * powf(fabsf(q), (float)(4.0 / 3.0)) * scale;
        __nv_bfloat16 h, m;
        bsplit2(v, &h, &m);
        dh[tid + j * 256] = h;
        dm[tid + j * 256] = m;
    }
}

// ---------------- window + overlap-add + crop (float4) --------------------
__global__ void k_ola(float* __restrict__ out) {
    int vid = blockIdx.x * blockDim.x + threadIdx.x;
    long long base = (long long)vid * 4;
    if (base >= (long long)Bv * Cv * Tv) return;
    int t  = (int)(base % Tv);
    int bc = (int)(base / Tv);
    int b  = bc >> 1;
    int c  = bc & 1;
    int fb = t >> 10;
    int na = t & 1023;
    int rowa = (b * Fv + fb + 1) * Cv + c;
    int rowb = (b * Fv + fb) * Cv + c;
    float4 r1 = *(const float4*)(g_TD + (size_t)rowa * Nv + na);
    float4 r2 = *(const float4*)(g_TD + (size_t)rowb * Nv + na + Mv);
    float4 w1 = *(const float4*)(g_W + na);
    float4 w2 = *(const float4*)(g_W + na + Mv);
    float4 o;
    o.x = r1.x * w1.x + r2.x * w2.x;
    o.y = r1.y * w1.y + r2.y * w2.y;
    o.z = r1.z * w1.z + r2.z * w2.z;
    o.w = r1.w * w1.w + r2.w * w2.w;
    *(float4*)(out + base) = o;
}

// ---------------- launch ----------------------------------------------------
extern "C" void kernel_launch(void* const* d_in, const int* in_sizes, int n_in,
                              void* d_out, int out_size) {
    const float* audio = (const float*)d_in[0];
    float* out = (float*)d_out;
    const int SMEM_BYTES = 2 * 40960;   // 81,920 B

    cudaFuncSetAttribute(k_bf_inv, cudaFuncAttributeMaxDynamicSharedMemorySize, SMEM_BYTES);

    k_tables<<<(Nv * Mv + 255) / 256, 256>>>();
    {
        long long tot = (long long)Rv * Nv / 4;
        k_frames<<<(unsigned)((tot + 255) / 256), 256>>>(audio);
    }
    k_gemm_fwd<<<dim3(Mv / 128, Rv / 64), 128>>>();
    k_gain_quant<<<NFRAME, 256>>>();
    k_bf_inv<<<dim3(Nv / 128, Rv / 128), 256, SMEM_BYTES>>>();
    {
        int tot = Bv * Cv * Tv / 4;
        k_ola<<<(tot + 255) / 256, 256>>>(out);
    }
}